// round 3
// baseline (speedup 1.0000x reference)
#include <cuda_runtime.h>
#include <math.h>

// Problem constants
#define LSEQ 8192
#define NFFT 16384          // 2*LSEQ = 4^7
#define DM   768
#define EMB  33
#define FO   64
#define SHIFT_C 0.05f
#define NT   1024           // FFT threads per CTA (32 warps)

// Padded shared layout: +4 float2 per 64 float2 (32B per 512B) -> conflict-free strided passes
#define PHYS(i) ((i) + (((i) >> 6) << 2))
#define DPAD 17408                                   // PHYS(16383)=17403, round up
#define NTW  4096                                    // N/4 twiddles
#define SMEM_BYTES ((DPAD + NTW) * (int)sizeof(float2))   // 172032 B

// ---------------- scratch (device globals: no allocations allowed) ----------
__device__ float  g_S[LSEQ * FO];                       // post-MLP activations
__device__ float  g_k[DM * LSEQ];                       // filter k[d][l]
__device__ __align__(16) float2 g_Kf[(size_t)DM * NFFT];// (spectrum + D) * (1/N), scrambled
__device__ float2 g_tw[NTW];                            // W_N^t, t < N/4

// ---------------- complex helpers ----------------
__device__ __forceinline__ float2 cadd(float2 a, float2 b){ return make_float2(a.x+b.x, a.y+b.y); }
__device__ __forceinline__ float2 csub(float2 a, float2 b){ return make_float2(a.x-b.x, a.y-b.y); }
__device__ __forceinline__ float2 cmul(float2 a, float2 b){
    return make_float2(a.x*b.x - a.y*b.y, a.x*b.y + a.y*b.x);
}
__device__ __forceinline__ float2 conjf2(float2 a){ return make_float2(a.x, -a.y); }

// radix-4 DIF forward core (no twiddle): a = F4 x, W4 = e^{-i pi/2}
__device__ __forceinline__ void bf4f(float2 x0, float2 x1, float2 x2, float2 x3,
                                     float2& a0, float2& a1, float2& a2, float2& a3) {
    float2 t0 = cadd(x0, x2), t1 = csub(x0, x2);
    float2 t2 = cadd(x1, x3), t3 = csub(x1, x3);
    float2 mi = make_float2(t3.y, -t3.x);              // -i * t3
    a0 = cadd(t0, t2);
    a1 = cadd(t1, mi);
    a2 = csub(t0, t2);
    a3 = csub(t1, mi);
}
// radix-4 inverse core (unscaled): x = conj(F4) a = 4*F4^{-1} a
__device__ __forceinline__ void bf4i(float2 x0, float2 x1, float2 x2, float2 x3,
                                     float2& a0, float2& a1, float2& a2, float2& a3) {
    float2 t0 = cadd(x0, x2), t1 = csub(x0, x2);
    float2 t2 = cadd(x1, x3), t3 = csub(x1, x3);
    float2 pi = make_float2(-t3.y, t3.x);              // +i * t3
    a0 = cadd(t0, t2);
    a1 = cadd(t1, pi);
    a2 = csub(t0, t2);
    a3 = csub(t1, pi);
}

// ---------------- register radix-16 cores (two fused radix-4 DIF stages) ----
// In-place on x[16]; spanLo = 1<<LS; x[r] lives at array position b + r*spanLo.
template<int LS>
__device__ __forceinline__ void fft16_fwd(float2* x, const float2* tw, int j) {
    const int step16 = NFFT >> (LS + 4);
    const int step4  = NFFT >> (LS + 2);
    #pragma unroll
    for (int c = 0; c < 4; c++) {
        float2 a0, a1, a2, a3;
        bf4f(x[c], x[c+4], x[c+8], x[c+12], a0, a1, a2, a3);
        float2 w1 = tw[(j + (c << LS)) * step16];
        float2 w2 = cmul(w1, w1), w3 = cmul(w2, w1);
        x[c]    = a0;
        x[c+4]  = cmul(a1, w1);
        x[c+8]  = cmul(a2, w2);
        x[c+12] = cmul(a3, w3);
    }
    float2 w1 = tw[j * step4];
    float2 w2 = cmul(w1, w1), w3 = cmul(w2, w1);
    #pragma unroll
    for (int m = 0; m < 4; m++) {
        float2 a0, a1, a2, a3;
        bf4f(x[4*m], x[4*m+1], x[4*m+2], x[4*m+3], a0, a1, a2, a3);
        x[4*m]   = a0;
        x[4*m+1] = cmul(a1, w1);
        x[4*m+2] = cmul(a2, w2);
        x[4*m+3] = cmul(a3, w3);
    }
}

template<int LS>
__device__ __forceinline__ void fft16_inv(float2* x, const float2* tw, int j) {
    const int step16 = NFFT >> (LS + 4);
    const int step4  = NFFT >> (LS + 2);
    float2 wl1 = conjf2(tw[j * step4]);
    float2 wl2 = cmul(wl1, wl1), wl3 = cmul(wl2, wl1);
    #pragma unroll
    for (int m = 0; m < 4; m++) {
        float2 z0 = x[4*m];
        float2 z1 = cmul(x[4*m+1], wl1);
        float2 z2 = cmul(x[4*m+2], wl2);
        float2 z3 = cmul(x[4*m+3], wl3);
        bf4i(z0, z1, z2, z3, x[4*m], x[4*m+1], x[4*m+2], x[4*m+3]);
    }
    #pragma unroll
    for (int c = 0; c < 4; c++) {
        float2 wh1 = conjf2(tw[(j + (c << LS)) * step16]);
        float2 wh2 = cmul(wh1, wh1), wh3 = cmul(wh2, wh1);
        float2 z0 = x[c];
        float2 z1 = cmul(x[c+4],  wh1);
        float2 z2 = cmul(x[c+8],  wh2);
        float2 z3 = cmul(x[c+12], wh3);
        bf4i(z0, z1, z2, z3, x[c], x[c+4], x[c+8], x[c+12]);
    }
}

// ---------------- shared-memory fused passes (one column per thread) --------
template<int LS>
__device__ __forceinline__ void pass_fwd(float2* d, const float2* tw, int tid) {
    const int j = tid & ((1 << LS) - 1);
    const int g = tid >> LS;
    const int b = (g << (LS + 4)) + j;
    float2 x[16];
    #pragma unroll
    for (int r = 0; r < 16; r++) x[r] = d[PHYS(b + (r << LS))];
    fft16_fwd<LS>(x, tw, j);
    #pragma unroll
    for (int r = 0; r < 16; r++) d[PHYS(b + (r << LS))] = x[r];
    __syncthreads();
}

template<int LS>
__device__ __forceinline__ void pass_inv(float2* d, const float2* tw, int tid) {
    const int j = tid & ((1 << LS) - 1);
    const int g = tid >> LS;
    const int b = (g << (LS + 4)) + j;
    float2 x[16];
    #pragma unroll
    for (int r = 0; r < 16; r++) x[r] = d[PHYS(b + (r << LS))];
    fft16_inv<LS>(x, tw, j);
    #pragma unroll
    for (int r = 0; r < 16; r++) d[PHYS(b + (r << LS))] = x[r];
    __syncthreads();
}

// ---------------- twiddle init (double-precision sincospi) ------------------
__global__ void twiddle_init_kernel() {
    int t = blockIdx.x * blockDim.x + threadIdx.x;
    if (t < NTW) {
        double s, c;
        sincospi(-2.0 * (double)t / (double)NFFT, &s, &c);
        g_tw[t] = make_float2((float)c, (float)s);
    }
}

// ---------------- filter MLP stages 1-3 -------------------------------------
__global__ void mlp_kernel(const float* __restrict__ z, const float* __restrict__ freq,
                           const float* __restrict__ W1, const float* __restrict__ b1,
                           const float* __restrict__ W2, const float* __restrict__ b2,
                           const float* __restrict__ W3, const float* __restrict__ b3) {
    __shared__ float zs[4][EMB];
    __shared__ float as[4][FO];
    __shared__ float bs[4][FO];
    const int tid = threadIdx.x;
    const int lg  = tid >> 6;
    const int f   = tid & 63;
    const int l   = blockIdx.x * 4 + lg;

    if (f < EMB) zs[lg][f] = z[l * EMB + f];
    __syncthreads();

    const float fr = freq[f];

    float acc = b1[f];
    #pragma unroll
    for (int e = 0; e < EMB; e++) acc += zs[lg][e] * W1[e * FO + f];
    as[lg][f] = sinf(fr * acc);
    __syncthreads();

    acc = b2[f];
    #pragma unroll
    for (int e = 0; e < FO; e++) acc += as[lg][e] * W2[e * FO + f];
    bs[lg][f] = sinf(fr * acc);
    __syncthreads();

    acc = b3[f];
    #pragma unroll
    for (int e = 0; e < FO; e++) acc += bs[lg][e] * W3[e * FO + f];
    g_S[l * FO + f] = sinf(fr * acc);
}

// ---------------- output projection + exponential modulation ----------------
__global__ void filt_kernel(const float* __restrict__ Wout, const float* __restrict__ t,
                            const float* __restrict__ deltas) {
    __shared__ float Ss[32][FO];
    __shared__ float Ws[FO][128];
    const int tid = threadIdx.x;
    const int l0  = blockIdx.x * 32;
    const int d0  = blockIdx.y * 128;

    for (int i = tid; i < 32 * FO; i += 256)
        Ss[i >> 6][i & 63] = g_S[(l0 + (i >> 6)) * FO + (i & 63)];
    for (int i = tid; i < FO * 128; i += 256)
        Ws[i >> 7][i & 127] = Wout[(i >> 7) * DM + d0 + (i & 127)];
    __syncthreads();

    const int dl  = tid & 127;
    const int lgp = tid >> 7;
    float acc[16];
    #pragma unroll
    for (int i = 0; i < 16; i++) acc[i] = 0.0f;
    #pragma unroll
    for (int f = 0; f < FO; f++) {
        const float w = Ws[f][dl];
        #pragma unroll
        for (int i = 0; i < 16; i++) acc[i] += Ss[lgp * 16 + i][f] * w;
    }
    const int d = d0 + dl;
    const float ad = fabsf(deltas[d]);
    #pragma unroll
    for (int i = 0; i < 16; i++) {
        const int l = l0 + lgp * 16 + i;
        g_k[(size_t)d * LSEQ + l] = acc[i] * (expf(-t[l] * ad) + SHIFT_C);
    }
}

// ---------------- kernel spectrum (+D baked in): 3 smem passes --------------
__global__ void __launch_bounds__(NT, 1)
kf_kernel(const float* __restrict__ Dbias) {
    extern __shared__ float2 sm[];
    float2* d  = sm;
    float2* tw = sm + DPAD;
    const int tid = threadIdx.x;
    const int ch  = blockIdx.x;

    for (int i = tid; i < NTW; i += NT) tw[i] = g_tw[i];
    __syncthreads();

    const float* krow = g_k + (size_t)ch * LSEQ;

    // P1: stages (6,5), LS=10, input fused from global (second half zero)
    {
        const int j = tid;
        float2 x[16];
        #pragma unroll
        for (int r = 0; r < 16; r++) {
            x[r] = (r < 8) ? make_float2(krow[j + (r << 10)], 0.0f)
                           : make_float2(0.0f, 0.0f);
        }
        fft16_fwd<10>(x, tw, j);
        #pragma unroll
        for (int r = 0; r < 16; r++) d[PHYS(j + (r << 10))] = x[r];
    }
    __syncthreads();

    pass_fwd<6>(d, tw, tid);   // stages (4,3)
    pass_fwd<2>(d, tw, tid);   // stages (2,1)

    // P4: stage 0 (twiddle = 1) + bake (spec + D) * 1/N, store to g_Kf
    float2* out = g_Kf + (size_t)ch * NFFT;
    const float sc = 1.0f / (float)NFFT;
    const float Dd = Dbias[ch];
    #pragma unroll
    for (int k = 0; k < 4; k++) {
        const int q = tid + k * NT;
        const int p = PHYS(4 * q);
        float4 lo = *reinterpret_cast<float4*>(&d[p]);
        float4 hi = *reinterpret_cast<float4*>(&d[p + 2]);
        float2 a0, a1, a2, a3;
        bf4f(make_float2(lo.x, lo.y), make_float2(lo.z, lo.w),
             make_float2(hi.x, hi.y), make_float2(hi.z, hi.w), a0, a1, a2, a3);
        float4 o01 = make_float4((a0.x + Dd) * sc, a0.y * sc, (a1.x + Dd) * sc, a1.y * sc);
        float4 o23 = make_float4((a2.x + Dd) * sc, a2.y * sc, (a3.x + Dd) * sc, a3.y * sc);
        reinterpret_cast<float4*>(out)[2 * q]     = o01;
        reinterpret_cast<float4*>(out)[2 * q + 1] = o23;
    }
}

// ---------------- conv: fwd, fused stage0*Kf*inv-stage0, inv ----------------
__global__ void __launch_bounds__(NT, 1)
conv_kernel(const float* __restrict__ x, float* __restrict__ out) {
    extern __shared__ float2 sm[];
    float2* d  = sm;
    float2* tw = sm + DPAD;
    const int tid = threadIdx.x;
    const int ch  = blockIdx.x;
    const int p   = blockIdx.y;                   // batch pair

    const float* u0 = x + ((size_t)(2*p)     * DM + ch) * LSEQ;
    const float* u1 = x + ((size_t)(2*p + 1) * DM + ch) * LSEQ;

    for (int i = tid; i < NTW; i += NT) tw[i] = g_tw[i];
    __syncthreads();

    // P1 fwd: stages (6,5), input fused from global (pack u0 + i*u1, pad zeros)
    {
        const int j = tid;
        float2 xv[16];
        #pragma unroll
        for (int r = 0; r < 16; r++) {
            if (r < 8) {
                const int i = j + (r << 10);
                xv[r] = make_float2(u0[i], u1[i]);
            } else {
                xv[r] = make_float2(0.0f, 0.0f);
            }
        }
        fft16_fwd<10>(xv, tw, j);
        #pragma unroll
        for (int r = 0; r < 16; r++) d[PHYS(j + (r << 10))] = xv[r];
    }
    __syncthreads();

    pass_fwd<6>(d, tw, tid);   // stages (4,3)
    pass_fwd<2>(d, tw, tid);   // stages (2,1)

    // Combined: fwd stage 0 -> pointwise * Kf (D baked in) -> inv stage 0
    const float2* kf = g_Kf + (size_t)ch * NFFT;
    #pragma unroll
    for (int k = 0; k < 4; k++) {
        const int q = tid + k * NT;
        const int pp = PHYS(4 * q);
        float4 lo = *reinterpret_cast<float4*>(&d[pp]);
        float4 hi = *reinterpret_cast<float4*>(&d[pp + 2]);
        float2 a0, a1, a2, a3;
        bf4f(make_float2(lo.x, lo.y), make_float2(lo.z, lo.w),
             make_float2(hi.x, hi.y), make_float2(hi.z, hi.w), a0, a1, a2, a3);
        const float4 k01 = reinterpret_cast<const float4*>(kf)[2 * q];
        const float4 k23 = reinterpret_cast<const float4*>(kf)[2 * q + 1];
        a0 = cmul(a0, make_float2(k01.x, k01.y));
        a1 = cmul(a1, make_float2(k01.z, k01.w));
        a2 = cmul(a2, make_float2(k23.x, k23.y));
        a3 = cmul(a3, make_float2(k23.z, k23.w));
        float2 z0, z1, z2, z3;
        bf4i(a0, a1, a2, a3, z0, z1, z2, z3);
        *reinterpret_cast<float4*>(&d[pp])     = make_float4(z0.x, z0.y, z1.x, z1.y);
        *reinterpret_cast<float4*>(&d[pp + 2]) = make_float4(z2.x, z2.y, z3.x, z3.y);
    }
    __syncthreads();

    pass_inv<2>(d, tw, tid);   // undo stages (1,2)
    pass_inv<6>(d, tw, tid);   // undo stages (3,4)

    // Final inv pass: stages (5,6), LS=10, direct global store (residual baked into Kf)
    float* o0 = out + ((size_t)(2*p)     * DM + ch) * LSEQ;
    float* o1 = out + ((size_t)(2*p + 1) * DM + ch) * LSEQ;
    {
        const int j = tid;
        float2 xv[16];
        #pragma unroll
        for (int r = 0; r < 16; r++) xv[r] = d[PHYS(j + (r << 10))];
        fft16_inv<10>(xv, tw, j);
        #pragma unroll
        for (int r = 0; r < 8; r++) {
            const int i = j + (r << 10);
            o0[i] = xv[r].x;
            o1[i] = xv[r].y;
        }
    }
}

// ---------------- launch ----------------------------------------------------
// Input order (metadata): x, z, t, freq, W1, b1, W2, b2, W3, b3, Wout, deltas, D
extern "C" void kernel_launch(void* const* d_in, const int* in_sizes, int n_in,
                              void* d_out, int out_size) {
    (void)in_sizes; (void)n_in; (void)out_size;
    const float* x      = (const float*)d_in[0];
    const float* z      = (const float*)d_in[1];
    const float* t      = (const float*)d_in[2];
    const float* freq   = (const float*)d_in[3];
    const float* W1     = (const float*)d_in[4];
    const float* b1     = (const float*)d_in[5];
    const float* W2     = (const float*)d_in[6];
    const float* b2     = (const float*)d_in[7];
    const float* W3     = (const float*)d_in[8];
    const float* b3     = (const float*)d_in[9];
    const float* Wout   = (const float*)d_in[10];
    const float* deltas = (const float*)d_in[11];
    const float* Dbias  = (const float*)d_in[12];
    float* out = (float*)d_out;

    cudaFuncSetAttribute(kf_kernel,   cudaFuncAttributeMaxDynamicSharedMemorySize, SMEM_BYTES);
    cudaFuncSetAttribute(conv_kernel, cudaFuncAttributeMaxDynamicSharedMemorySize, SMEM_BYTES);

    twiddle_init_kernel<<<NTW / 512, 512>>>();
    mlp_kernel<<<LSEQ / 4, 256>>>(z, freq, W1, b1, W2, b2, W3, b3);
    filt_kernel<<<dim3(LSEQ / 32, DM / 128), 256>>>(Wout, t, deltas);
    kf_kernel<<<DM, NT, SMEM_BYTES>>>(Dbias);
    conv_kernel<<<dim3(DM, 2), NT, SMEM_BYTES>>>(x, out);
}

// round 4
// speedup vs baseline: 1.2350x; 1.2350x over previous
#include <cuda_runtime.h>
#include <math.h>

// Problem constants
#define LSEQ 8192
#define NFFT 16384          // 2*LSEQ = 4^7
#define DM   768
#define EMB  33
#define FO   64
#define SHIFT_C 0.05f
#define NT   512            // FFT threads per CTA (2 radix-16 columns per thread)

// Padded shared layout: +4 float2 per 64 float2 -> conflict-free strided passes
#define PHYS(i) ((i) + (((i) >> 6) << 2))
#define DPAD 17408
#define SMEM_BYTES (DPAD * (int)sizeof(float2))     // 139264 B

// ---------------- scratch (device globals: no allocations allowed) ----------
__device__ float  g_S[LSEQ * FO];                       // post-MLP activations
__device__ float  g_k[DM * LSEQ];                       // filter k[d][l]
__device__ __align__(16) float2 g_Kf[(size_t)DM * NFFT];// (spectrum + D) * (1/N), scrambled

// ---------------- complex helpers ----------------
__device__ __forceinline__ float2 cadd(float2 a, float2 b){ return make_float2(a.x+b.x, a.y+b.y); }
__device__ __forceinline__ float2 csub(float2 a, float2 b){ return make_float2(a.x-b.x, a.y-b.y); }
__device__ __forceinline__ float2 cmul(float2 a, float2 b){
    return make_float2(a.x*b.x - a.y*b.y, a.x*b.y + a.y*b.x);
}

// radix-4 DIF forward core (no twiddle): a = F4 x
__device__ __forceinline__ void bf4f(float2 x0, float2 x1, float2 x2, float2 x3,
                                     float2& a0, float2& a1, float2& a2, float2& a3) {
    float2 t0 = cadd(x0, x2), t1 = csub(x0, x2);
    float2 t2 = cadd(x1, x3), t3 = csub(x1, x3);
    float2 mi = make_float2(t3.y, -t3.x);              // -i * t3
    a0 = cadd(t0, t2);
    a1 = cadd(t1, mi);
    a2 = csub(t0, t2);
    a3 = csub(t1, mi);
}
// radix-4 inverse core (unscaled): x = conj(F4) a
__device__ __forceinline__ void bf4i(float2 x0, float2 x1, float2 x2, float2 x3,
                                     float2& a0, float2& a1, float2& a2, float2& a3) {
    float2 t0 = cadd(x0, x2), t1 = csub(x0, x2);
    float2 t2 = cadd(x1, x3), t3 = csub(x1, x3);
    float2 pi = make_float2(-t3.y, t3.x);              // +i * t3
    a0 = cadd(t0, t2);
    a1 = cadd(t1, pi);
    a2 = csub(t0, t2);
    a3 = csub(t1, pi);
}

// e^{-i pi c/8} rotation constants (forward)
#define RC1X 0.92387953251128674f
#define RC1Y 0.38268343236508977f
#define RC2X 0.70710678118654752f

// ---------------- register radix-16 cores, twiddles computed on the fly -----
// All twiddles derive from b = exp(-2*pi*i * j / 2^(LS+4)):
//   high substage c: w1 = b * e^{-i pi c/8};  low substage: w1 = b^4.
template<int LS>
__device__ __forceinline__ void fft16_fwd(float2* x, int j) {
    const float C = -6.2831853071795864769f / (float)(1 << (LS + 4));
    float sb, cb;
    __sincosf(C * (float)j, &sb, &cb);
    const float2 b  = make_float2(cb, sb);
    const float2 b2 = cmul(b, b);
    const float2 b4 = cmul(b2, b2);
    float2 W1[4];
    W1[0] = b;
    W1[1] = cmul(b, make_float2(RC1X, -RC1Y));
    W1[2] = cmul(b, make_float2(RC2X, -RC2X));
    W1[3] = cmul(b, make_float2(RC1Y, -RC1X));
    #pragma unroll
    for (int c = 0; c < 4; c++) {
        float2 a0, a1, a2, a3;
        bf4f(x[c], x[c+4], x[c+8], x[c+12], a0, a1, a2, a3);
        float2 w1 = W1[c];
        float2 w2 = cmul(w1, w1), w3 = cmul(w2, w1);
        x[c]    = a0;
        x[c+4]  = cmul(a1, w1);
        x[c+8]  = cmul(a2, w2);
        x[c+12] = cmul(a3, w3);
    }
    float2 w1 = b4;
    float2 w2 = cmul(w1, w1), w3 = cmul(w2, w1);
    #pragma unroll
    for (int m = 0; m < 4; m++) {
        float2 a0, a1, a2, a3;
        bf4f(x[4*m], x[4*m+1], x[4*m+2], x[4*m+3], a0, a1, a2, a3);
        x[4*m]   = a0;
        x[4*m+1] = cmul(a1, w1);
        x[4*m+2] = cmul(a2, w2);
        x[4*m+3] = cmul(a3, w3);
    }
}

template<int LS>
__device__ __forceinline__ void fft16_inv(float2* x, int j) {
    const float C = -6.2831853071795864769f / (float)(1 << (LS + 4));
    float sb, cb;
    __sincosf(C * (float)j, &sb, &cb);
    const float2 b  = make_float2(cb, -sb);            // conj(b)
    const float2 b2 = cmul(b, b);
    const float2 b4 = cmul(b2, b2);
    float2 wl1 = b4;
    float2 wl2 = cmul(wl1, wl1), wl3 = cmul(wl2, wl1);
    #pragma unroll
    for (int m = 0; m < 4; m++) {
        float2 z0 = x[4*m];
        float2 z1 = cmul(x[4*m+1], wl1);
        float2 z2 = cmul(x[4*m+2], wl2);
        float2 z3 = cmul(x[4*m+3], wl3);
        bf4i(z0, z1, z2, z3, x[4*m], x[4*m+1], x[4*m+2], x[4*m+3]);
    }
    float2 WH[4];
    WH[0] = b;
    WH[1] = cmul(b, make_float2(RC1X,  RC1Y));
    WH[2] = cmul(b, make_float2(RC2X,  RC2X));
    WH[3] = cmul(b, make_float2(RC1Y,  RC1X));
    #pragma unroll
    for (int c = 0; c < 4; c++) {
        float2 wh1 = WH[c];
        float2 wh2 = cmul(wh1, wh1), wh3 = cmul(wh2, wh1);
        float2 z0 = x[c];
        float2 z1 = cmul(x[c+4],  wh1);
        float2 z2 = cmul(x[c+8],  wh2);
        float2 z3 = cmul(x[c+12], wh3);
        bf4i(z0, z1, z2, z3, x[c], x[c+4], x[c+8], x[c+12]);
    }
}

// ---------------- shared-memory fused passes (2 columns per thread) ---------
template<int LS>
__device__ __forceinline__ void pass_fwd(float2* d, int tid) {
    #pragma unroll
    for (int k = 0; k < 2; k++) {
        const int c = tid + k * NT;
        const int j = c & ((1 << LS) - 1);
        const int g = c >> LS;
        const int b = (g << (LS + 4)) + j;
        float2 x[16];
        #pragma unroll
        for (int r = 0; r < 16; r++) x[r] = d[PHYS(b + (r << LS))];
        fft16_fwd<LS>(x, j);
        #pragma unroll
        for (int r = 0; r < 16; r++) d[PHYS(b + (r << LS))] = x[r];
    }
    __syncthreads();
}

template<int LS>
__device__ __forceinline__ void pass_inv(float2* d, int tid) {
    #pragma unroll
    for (int k = 0; k < 2; k++) {
        const int c = tid + k * NT;
        const int j = c & ((1 << LS) - 1);
        const int g = c >> LS;
        const int b = (g << (LS + 4)) + j;
        float2 x[16];
        #pragma unroll
        for (int r = 0; r < 16; r++) x[r] = d[PHYS(b + (r << LS))];
        fft16_inv<LS>(x, j);
        #pragma unroll
        for (int r = 0; r < 16; r++) d[PHYS(b + (r << LS))] = x[r];
    }
    __syncthreads();
}

// ---------------- filter MLP stages 1-3 -------------------------------------
__global__ void mlp_kernel(const float* __restrict__ z, const float* __restrict__ freq,
                           const float* __restrict__ W1, const float* __restrict__ b1,
                           const float* __restrict__ W2, const float* __restrict__ b2,
                           const float* __restrict__ W3, const float* __restrict__ b3) {
    __shared__ float zs[4][EMB];
    __shared__ float as[4][FO];
    __shared__ float bs[4][FO];
    const int tid = threadIdx.x;
    const int lg  = tid >> 6;
    const int f   = tid & 63;
    const int l   = blockIdx.x * 4 + lg;

    if (f < EMB) zs[lg][f] = z[l * EMB + f];
    __syncthreads();

    const float fr = freq[f];

    float acc = b1[f];
    #pragma unroll
    for (int e = 0; e < EMB; e++) acc += zs[lg][e] * W1[e * FO + f];
    as[lg][f] = sinf(fr * acc);
    __syncthreads();

    acc = b2[f];
    #pragma unroll
    for (int e = 0; e < FO; e++) acc += as[lg][e] * W2[e * FO + f];
    bs[lg][f] = sinf(fr * acc);
    __syncthreads();

    acc = b3[f];
    #pragma unroll
    for (int e = 0; e < FO; e++) acc += bs[lg][e] * W3[e * FO + f];
    g_S[l * FO + f] = sinf(fr * acc);
}

// ---------------- output projection + exponential modulation ----------------
__global__ void filt_kernel(const float* __restrict__ Wout, const float* __restrict__ t,
                            const float* __restrict__ deltas) {
    __shared__ float Ss[32][FO];
    __shared__ float Ws[FO][128];
    const int tid = threadIdx.x;
    const int l0  = blockIdx.x * 32;
    const int d0  = blockIdx.y * 128;

    for (int i = tid; i < 32 * FO; i += 256)
        Ss[i >> 6][i & 63] = g_S[(l0 + (i >> 6)) * FO + (i & 63)];
    for (int i = tid; i < FO * 128; i += 256)
        Ws[i >> 7][i & 127] = Wout[(i >> 7) * DM + d0 + (i & 127)];
    __syncthreads();

    const int dl  = tid & 127;
    const int lgp = tid >> 7;
    float acc[16];
    #pragma unroll
    for (int i = 0; i < 16; i++) acc[i] = 0.0f;
    #pragma unroll
    for (int f = 0; f < FO; f++) {
        const float w = Ws[f][dl];
        #pragma unroll
        for (int i = 0; i < 16; i++) acc[i] += Ss[lgp * 16 + i][f] * w;
    }
    const int d = d0 + dl;
    const float ad = fabsf(deltas[d]);
    #pragma unroll
    for (int i = 0; i < 16; i++) {
        const int l = l0 + lgp * 16 + i;
        g_k[(size_t)d * LSEQ + l] = acc[i] * (expf(-t[l] * ad) + SHIFT_C);
    }
}

// ---------------- kernel spectrum (+D baked in): 3 smem passes --------------
__global__ void __launch_bounds__(NT, 1)
kf_kernel(const float* __restrict__ Dbias) {
    extern __shared__ float2 sm[];
    float2* d = sm;
    const int tid = threadIdx.x;
    const int ch  = blockIdx.x;

    const float* krow = g_k + (size_t)ch * LSEQ;

    // P1: stages (6,5), LS=10, input fused from global (second half zero)
    #pragma unroll
    for (int k = 0; k < 2; k++) {
        const int j = tid + k * NT;
        float2 x[16];
        #pragma unroll
        for (int r = 0; r < 16; r++) {
            x[r] = (r < 8) ? make_float2(krow[j + (r << 10)], 0.0f)
                           : make_float2(0.0f, 0.0f);
        }
        fft16_fwd<10>(x, j);
        #pragma unroll
        for (int r = 0; r < 16; r++) d[PHYS(j + (r << 10))] = x[r];
    }
    __syncthreads();

    pass_fwd<6>(d, tid);   // stages (4,3)
    pass_fwd<2>(d, tid);   // stages (2,1)

    // P4: stage 0 (twiddle = 1) + bake (spec + D) * 1/N, store to g_Kf
    float2* out = g_Kf + (size_t)ch * NFFT;
    const float sc = 1.0f / (float)NFFT;
    const float Dd = Dbias[ch];
    #pragma unroll
    for (int k = 0; k < 8; k++) {
        const int q = tid + k * NT;
        const int p = PHYS(4 * q);
        float4 lo = *reinterpret_cast<float4*>(&d[p]);
        float4 hi = *reinterpret_cast<float4*>(&d[p + 2]);
        float2 a0, a1, a2, a3;
        bf4f(make_float2(lo.x, lo.y), make_float2(lo.z, lo.w),
             make_float2(hi.x, hi.y), make_float2(hi.z, hi.w), a0, a1, a2, a3);
        float4 o01 = make_float4((a0.x + Dd) * sc, a0.y * sc, (a1.x + Dd) * sc, a1.y * sc);
        float4 o23 = make_float4((a2.x + Dd) * sc, a2.y * sc, (a3.x + Dd) * sc, a3.y * sc);
        reinterpret_cast<float4*>(out)[2 * q]     = o01;
        reinterpret_cast<float4*>(out)[2 * q + 1] = o23;
    }
}

// ---------------- conv: fwd, fused stage0*Kf*inv-stage0, inv ----------------
__global__ void __launch_bounds__(NT, 1)
conv_kernel(const float* __restrict__ x, float* __restrict__ out) {
    extern __shared__ float2 sm[];
    float2* d = sm;
    const int tid = threadIdx.x;
    const int ch  = blockIdx.x;
    const int p   = blockIdx.y;                   // batch pair

    const float* u0 = x + ((size_t)(2*p)     * DM + ch) * LSEQ;
    const float* u1 = x + ((size_t)(2*p + 1) * DM + ch) * LSEQ;

    // P1 fwd: stages (6,5), input fused from global (pack u0 + i*u1, pad zeros)
    #pragma unroll
    for (int k = 0; k < 2; k++) {
        const int j = tid + k * NT;
        float2 xv[16];
        #pragma unroll
        for (int r = 0; r < 16; r++) {
            if (r < 8) {
                const int i = j + (r << 10);
                xv[r] = make_float2(u0[i], u1[i]);
            } else {
                xv[r] = make_float2(0.0f, 0.0f);
            }
        }
        fft16_fwd<10>(xv, j);
        #pragma unroll
        for (int r = 0; r < 16; r++) d[PHYS(j + (r << 10))] = xv[r];
    }
    __syncthreads();

    pass_fwd<6>(d, tid);   // stages (4,3)
    pass_fwd<2>(d, tid);   // stages (2,1)

    // Combined: fwd stage 0 -> pointwise * Kf (D baked in) -> inv stage 0
    const float2* kf = g_Kf + (size_t)ch * NFFT;
    #pragma unroll
    for (int k = 0; k < 8; k++) {
        const int q = tid + k * NT;
        const int pp = PHYS(4 * q);
        float4 lo = *reinterpret_cast<float4*>(&d[pp]);
        float4 hi = *reinterpret_cast<float4*>(&d[pp + 2]);
        float2 a0, a1, a2, a3;
        bf4f(make_float2(lo.x, lo.y), make_float2(lo.z, lo.w),
             make_float2(hi.x, hi.y), make_float2(hi.z, hi.w), a0, a1, a2, a3);
        const float4 k01 = reinterpret_cast<const float4*>(kf)[2 * q];
        const float4 k23 = reinterpret_cast<const float4*>(kf)[2 * q + 1];
        a0 = cmul(a0, make_float2(k01.x, k01.y));
        a1 = cmul(a1, make_float2(k01.z, k01.w));
        a2 = cmul(a2, make_float2(k23.x, k23.y));
        a3 = cmul(a3, make_float2(k23.z, k23.w));
        float2 z0, z1, z2, z3;
        bf4i(a0, a1, a2, a3, z0, z1, z2, z3);
        *reinterpret_cast<float4*>(&d[pp])     = make_float4(z0.x, z0.y, z1.x, z1.y);
        *reinterpret_cast<float4*>(&d[pp + 2]) = make_float4(z2.x, z2.y, z3.x, z3.y);
    }
    __syncthreads();

    pass_inv<2>(d, tid);   // undo stages (1,2)
    pass_inv<6>(d, tid);   // undo stages (3,4)

    // Final inv pass: stages (5,6), LS=10, direct global store
    float* o0 = out + ((size_t)(2*p)     * DM + ch) * LSEQ;
    float* o1 = out + ((size_t)(2*p + 1) * DM + ch) * LSEQ;
    #pragma unroll
    for (int k = 0; k < 2; k++) {
        const int j = tid + k * NT;
        float2 xv[16];
        #pragma unroll
        for (int r = 0; r < 16; r++) xv[r] = d[PHYS(j + (r << 10))];
        fft16_inv<10>(xv, j);
        #pragma unroll
        for (int r = 0; r < 8; r++) {
            const int i = j + (r << 10);
            o0[i] = xv[r].x;
            o1[i] = xv[r].y;
        }
    }
}

// ---------------- launch ----------------------------------------------------
// Input order (metadata): x, z, t, freq, W1, b1, W2, b2, W3, b3, Wout, deltas, D
extern "C" void kernel_launch(void* const* d_in, const int* in_sizes, int n_in,
                              void* d_out, int out_size) {
    (void)in_sizes; (void)n_in; (void)out_size;
    const float* x      = (const float*)d_in[0];
    const float* z      = (const float*)d_in[1];
    const float* t      = (const float*)d_in[2];
    const float* freq   = (const float*)d_in[3];
    const float* W1     = (const float*)d_in[4];
    const float* b1     = (const float*)d_in[5];
    const float* W2     = (const float*)d_in[6];
    const float* b2     = (const float*)d_in[7];
    const float* W3     = (const float*)d_in[8];
    const float* b3     = (const float*)d_in[9];
    const float* Wout   = (const float*)d_in[10];
    const float* deltas = (const float*)d_in[11];
    const float* Dbias  = (const float*)d_in[12];
    float* out = (float*)d_out;

    cudaFuncSetAttribute(kf_kernel,   cudaFuncAttributeMaxDynamicSharedMemorySize, SMEM_BYTES);
    cudaFuncSetAttribute(conv_kernel, cudaFuncAttributeMaxDynamicSharedMemorySize, SMEM_BYTES);

    mlp_kernel<<<LSEQ / 4, 256>>>(z, freq, W1, b1, W2, b2, W3, b3);
    filt_kernel<<<dim3(LSEQ / 32, DM / 128), 256>>>(Wout, t, deltas);
    kf_kernel<<<DM, NT, SMEM_BYTES>>>(Dbias);
    conv_kernel<<<dim3(DM, 2), NT, SMEM_BYTES>>>(x, out);
}